// round 10
// baseline (speedup 1.0000x reference)
#include <cuda_runtime.h>
#include <cuda_fp16.h>
#include <mma.h>
#include <cstdint>

using namespace nvcuda;

#define N_IMG 64
#define C_IN  64
#define H_IN  56
#define W_IN  56
#define HW_IN (H_IN * W_IN)
#define K_OUT 128
#define H_OUT 54
#define W_OUT 54
#define PQ    (H_OUT * W_OUT)          /* 2916   */
#define NPQ   (N_IMG * PQ)             /* 186624 */

#define M_TILE 128
#define NTILES (NPQ / M_TILE)          /* 1458 exact */
#define NTAPS  9

#define LDA_H 72                        /* A row stride in halves (144 B)  */
#define LDB_H 136                       /* B row stride in halves (272 B)  */
#define LDO   132                       /* epilogue staging stride, floats */

#define B_TAP   (64 * LDB_H * 2)        /* 17408 per tap                  */
#define A_STAGE (128 * LDA_H * 2)       /* 18432 per stage                */
#define OFF_B   0
#define OFF_A   (NTAPS * B_TAP)         /* 156672 */
#define OFF_OS  (OFF_A + 3 * A_STAGE)   /* 211968 */
#define OFF_TAB (OFF_OS + 32 * LDO * 4) /* 228864 (Os = 16896) */
#define SMEM_TOTAL (OFF_TAB + 2560)     /* 231424 */

/* x as NHWC fp16 (int8-valued, exact) */
__device__ __half g_xh[(size_t)N_IMG * H_IN * W_IN * C_IN];
/* weights [tap][c][ko] fp16 */
__device__ __half g_wh[NTAPS * C_IN * K_OUT];

__device__ __forceinline__ uint32_t smem_u32(const void* p) {
    uint32_t a;
    asm("{ .reg .u64 t; cvta.to.shared.u64 t, %1; cvt.u32.u64 %0, t; }"
        : "=r"(a) : "l"(p));
    return a;
}
#define CP16(dst, src) \
    asm volatile("cp.async.cg.shared.global [%0], [%1], 16;" \
                 :: "r"(dst), "l"(src) : "memory")
#define CP_COMMIT() asm volatile("cp.async.commit_group;" ::: "memory")
#define CP_WAIT1()  asm volatile("cp.async.wait_group 1;" ::: "memory")
#define CP_WAIT0()  asm volatile("cp.async.wait_group 0;" ::: "memory")

/* ====== prep: clamp+trunc fp32 NCHW -> fp16 NHWC, + weight transform ====== */
__global__ void __launch_bounds__(256) prep_kernel(const float* __restrict__ x,
                                                   const float* __restrict__ w) {
    if (blockIdx.x >= N_IMG * H_IN) {
        /* weight transform: OIHW fp32 -> [tap][c][ko] fp16 */
        int i = (blockIdx.x - N_IMG * H_IN) * 256 + threadIdx.x;
        int ko  = i & 127;
        int c   = (i >> 7) & 63;
        int tap = i >> 13;
        int r = tap / 3, s = tap - 3 * (tap / 3);
        g_wh[i] = __float2half_rn(w[((ko * C_IN + c) * 3 + r) * 3 + s]);
        return;
    }
    __shared__ __half tile[C_IN * 60];         /* stride 60: 8B-aligned rows */
    int np = blockIdx.x;                       /* n*56 + p */
    int n = np / H_IN, p = np - n * H_IN;
    const float* src = x + (size_t)n * C_IN * HW_IN + p * W_IN;

    for (int i = threadIdx.x; i < 896; i += 256) {
        int c = i / 14, qg = i - c * 14;
        float4 v = *(const float4*)(src + c * HW_IN + qg * 4);
        union { __half h[4]; uint2 u; } pk;
        pk.h[0] = __float2half_rn((float)(int)fminf(fmaxf(v.x, -128.f), 127.f));
        pk.h[1] = __float2half_rn((float)(int)fminf(fmaxf(v.y, -128.f), 127.f));
        pk.h[2] = __float2half_rn((float)(int)fminf(fmaxf(v.z, -128.f), 127.f));
        pk.h[3] = __float2half_rn((float)(int)fminf(fmaxf(v.w, -128.f), 127.f));
        *(uint2*)&tile[c * 60 + qg * 4] = pk.u;
    }
    __syncthreads();

    uint4* dst = (uint4*)(g_xh + (size_t)np * (W_IN * C_IN));
    for (int i = threadIdx.x; i < 448; i += 256) {
        int q = i >> 3, c8 = i & 7;
        union { __half h[8]; uint4 u; } pk;
#pragma unroll
        for (int j = 0; j < 8; j++) pk.h[j] = tile[(c8 * 8 + j) * 60 + q];
        dst[q * 8 + c8] = pk.u;
    }
}

/* ==== main: persistent CTAs, resident B, fp16 HMMA, cp.async A ring ======= */
extern __shared__ unsigned char smem_raw[];

__global__ void __launch_bounds__(256, 1)
conv_kernel(const float* __restrict__ bias, float* __restrict__ out) {
    unsigned char* sm = smem_raw;
    const uint32_t smem_base = smem_u32(sm);
    const int tid = threadIdx.x;
    const int bid = blockIdx.x;
    const int nsm = gridDim.x;

    int*   in_tab  = (int*)(sm + OFF_TAB);       /* [2][128] */
    int*   out_tab = in_tab + 256;               /* [2][128] */
    float* bias_s  = (float*)(out_tab + 256);    /* [128]    */

    const int count = (NTILES - bid + nsm - 1) / nsm;   /* tiles for this CTA */
    const int total = count * NTAPS;

    /* fill offset table for a tile into slot */
    auto fill_tab = [&](int tile, int slot) {
        if (tid < 128) {
            int gm  = tile * M_TILE + tid;
            int n   = gm / PQ;
            int rem = gm - n * PQ;
            int p   = rem / W_OUT;
            int q   = rem - p * W_OUT;
            in_tab[slot * 128 + tid]  = ((n * H_IN + p) * W_IN + q) * C_IN;
            out_tab[slot * 128 + tid] = n * (K_OUT * PQ) + rem;
        }
    };

    fill_tab(bid, 0);
    if (tid < 128) bias_s[tid] = bias[tid];
    __syncthreads();

    /* ---- prologue: resident B, all taps (group 0) ---- */
    {
        const unsigned char* wb = (const unsigned char*)g_wh;
#pragma unroll
        for (int j = 0; j < 36; j++) {           /* 9216 16B chunks / 256 thr */
            int i    = tid + j * 256;
            int tap  = i >> 10;
            int rem  = i & 1023;
            int k    = rem >> 4;
            int c16  = rem & 15;
            CP16(smem_base + OFF_B + tap * B_TAP + k * (LDB_H * 2) + c16 * 16,
                 wb + tap * 16384 + k * 256 + c16 * 16);
        }
        CP_COMMIT();
    }

    const int seg = tid & 7;                     /* A: 8 x 16B per pixel row */
    const int px0 = tid >> 3;

    auto load_A = [&](int tap, int slot, int stg) {
        uint32_t base = smem_base + OFF_A + stg * A_STAGE;
        int r = tap / 3, s = tap - 3 * (tap / 3);
        int tap_e = (r * W_IN + s) * C_IN;
        const unsigned char* xb = (const unsigned char*)g_xh;
#pragma unroll
        for (int j = 0; j < 4; j++) {
            int px = px0 + 32 * j;
            const void* src = xb +
                (size_t)(in_tab[slot * 128 + px] + tap_e) * 2 + seg * 16;
            CP16(base + px * (LDA_H * 2) + seg * 16, src);
        }
    };

    load_A(0, 0, 0);
    CP_COMMIT();
    if (total > 1) { load_A(1, 0, 1); CP_COMMIT(); }

    const int warp_m = (tid >> 5) & 1;
    const int warp_n = (tid >> 6);
    const int m0 = warp_m * 64;
    const int n0 = warp_n * 32;

    wmma::fragment<wmma::accumulator, 16, 16, 16, float> acc[4][2];
#pragma unroll
    for (int i = 0; i < 4; i++)
#pragma unroll
        for (int j = 0; j < 2; j++)
            wmma::fill_fragment(acc[i][j], 0.0f);

    int tap = 0, tseq = 0, stg = 0;
    int ptap = 2, ptseq = 0, pstg = 2;           /* prefetch cursor (g+2) */

    for (int g = 0; g < total; g++) {
        if (g < total - 1) CP_WAIT1();
        else               CP_WAIT0();
        __syncthreads();

        if (tap == 1 && tseq + 1 < count)
            fill_tab(bid + (tseq + 1) * nsm, (tseq + 1) & 1);

        if (g + 2 < total) {
            load_A(ptap, ptseq & 1, pstg);
            CP_COMMIT();
            if (++ptap == NTAPS) { ptap = 0; ++ptseq; }
            if (++pstg == 3) pstg = 0;
        }

        const __half* As = (const __half*)(sm + OFF_A + stg * A_STAGE);
        const __half* Bs = (const __half*)(sm + OFF_B + tap * B_TAP);
#pragma unroll
        for (int kk = 0; kk < 4; kk++) {
            wmma::fragment<wmma::matrix_a, 16, 16, 16, __half,
                           wmma::row_major> a[4];
            wmma::fragment<wmma::matrix_b, 16, 16, 16, __half,
                           wmma::row_major> b[2];
#pragma unroll
            for (int i = 0; i < 4; i++)
                wmma::load_matrix_sync(a[i],
                    As + (m0 + i * 16) * LDA_H + kk * 16, LDA_H);
#pragma unroll
            for (int j = 0; j < 2; j++)
                wmma::load_matrix_sync(b[j],
                    Bs + (kk * 16) * LDB_H + n0 + j * 16, LDB_H);
#pragma unroll
            for (int i = 0; i < 4; i++)
#pragma unroll
                for (int j = 0; j < 2; j++)
                    wmma::mma_sync(acc[i][j], a[i], b[j], acc[i][j]);
        }

        if (tap == 8) {
            /* ---- epilogue: four 32-ko passes through Os staging ---- */
            float* Os = (float*)(sm + OFF_OS);
            const int oslot = (tseq & 1) * 128;
#pragma unroll
            for (int pass = 0; pass < 4; pass++) {
                if (warp_n == pass) {
#pragma unroll
                    for (int i = 0; i < 4; i++)
#pragma unroll
                        for (int j = 0; j < 2; j++)
                            wmma::store_matrix_sync(
                                Os + (j * 16) * LDO + m0 + i * 16,
                                acc[i][j], LDO, wmma::mem_col_major);
                }
                __syncthreads();
#pragma unroll
                for (int u = 0; u < 16; u++) {
                    int idx  = tid + u * 256;
                    int ko_l = idx >> 7;
                    int m    = idx & 127;
                    int ko   = pass * 32 + ko_l;
                    out[out_tab[oslot + m] + ko * PQ] =
                        Os[ko_l * LDO + m] + bias_s[ko];
                }
                __syncthreads();
            }
#pragma unroll
            for (int i = 0; i < 4; i++)
#pragma unroll
                for (int j = 0; j < 2; j++)
                    wmma::fill_fragment(acc[i][j], 0.0f);
        }

        if (++tap == NTAPS) { tap = 0; ++tseq; }
        if (++stg == 3) stg = 0;
    }
}

/* ========================================================================= */
extern "C" void kernel_launch(void* const* d_in, const int* in_sizes, int n_in,
                              void* d_out, int out_size) {
    const float* x    = (const float*)d_in[0];
    const float* w    = (const float*)d_in[1];
    const float* bias = (const float*)d_in[2];
    float* out = (float*)d_out;

    cudaFuncSetAttribute(conv_kernel,
                         cudaFuncAttributeMaxDynamicSharedMemorySize,
                         SMEM_TOTAL);

    int dev = 0, nsm = 148;
    cudaGetDevice(&dev);
    cudaDeviceGetAttribute(&nsm, cudaDevAttrMultiProcessorCount, dev);
    if (nsm > NTILES) nsm = NTILES;

    prep_kernel<<<N_IMG * H_IN + 288, 256>>>(x, w);
    conv_kernel<<<nsm, 256, SMEM_TOTAL>>>(bias, out);
}

// round 11
// speedup vs baseline: 1.1233x; 1.1233x over previous
#include <cuda_runtime.h>
#include <cuda_fp16.h>
#include <mma.h>
#include <cstdint>

using namespace nvcuda;

#define N_IMG 64
#define C_IN  64
#define H_IN  56
#define W_IN  56
#define HW_IN (H_IN * W_IN)
#define K_OUT 128
#define H_OUT 54
#define W_OUT 54
#define PQ    (H_OUT * W_OUT)          /* 2916   */
#define NPQ   (N_IMG * PQ)             /* 186624 */

#define M_TILE 128
#define NCTA   (NPQ / M_TILE)          /* 1458 exact */
#define NTAPS  9

#define LDA_H 72                        /* A row stride in halves (144 B)  */
#define LDB_H 136                       /* B row stride in halves (272 B)  */
#define LDO   132                       /* epilogue staging stride, floats */

#define A_BYTES (128 * LDA_H * 2)       /* 18432 */
#define B_BYTES (64 * LDB_H * 2)        /* 17408 */
#define STAGE   (A_BYTES + B_BYTES)     /* 35840 */
#define OFF_STG 2048
#define SMEM_TOTAL (OFF_STG + 2 * STAGE)   /* 73728 */

/* x as NHWC fp16 (int8-valued, exact) */
__device__ __half g_xh[(size_t)N_IMG * H_IN * W_IN * C_IN];
/* weights [tap][c][ko] fp16 */
__device__ __half g_wh[NTAPS * C_IN * K_OUT];

__device__ __forceinline__ uint32_t smem_u32(const void* p) {
    uint32_t a;
    asm("{ .reg .u64 t; cvta.to.shared.u64 t, %1; cvt.u32.u64 %0, t; }"
        : "=r"(a) : "l"(p));
    return a;
}
#define CP16(dst, src) \
    asm volatile("cp.async.cg.shared.global [%0], [%1], 16;" \
                 :: "r"(dst), "l"(src) : "memory")
#define CP_COMMIT() asm volatile("cp.async.commit_group;" ::: "memory")
#define CP_WAIT0()  asm volatile("cp.async.wait_group 0;" ::: "memory")

/* ====== prep: clamp+trunc fp32 NCHW -> fp16 NHWC, + weight transform ====== */
__global__ void __launch_bounds__(256) prep_kernel(const float* __restrict__ x,
                                                   const float* __restrict__ w) {
    if (blockIdx.x >= N_IMG * H_IN) {
        /* weight transform: OIHW fp32 -> [tap][c][ko] fp16 (288 blocks) */
        int i = (blockIdx.x - N_IMG * H_IN) * 256 + threadIdx.x;
        int ko  = i & 127;
        int c   = (i >> 7) & 63;
        int tap = i >> 13;
        int r = tap / 3, s = tap - 3 * (tap / 3);
        g_wh[i] = __float2half_rn(w[((ko * C_IN + c) * 3 + r) * 3 + s]);
        return;
    }
    __shared__ __half tile[C_IN * 60];         /* stride 60: 8B-aligned rows */
    int np = blockIdx.x;                       /* n*56 + p */
    int n = np / H_IN, p = np - n * H_IN;
    const float* src = x + (size_t)n * C_IN * HW_IN + p * W_IN;

    for (int i = threadIdx.x; i < 896; i += 256) {
        int c = i / 14, qg = i - c * 14;
        float4 v = *(const float4*)(src + c * HW_IN + qg * 4);
        union { __half h[4]; uint2 u; } pk;
        pk.h[0] = __float2half_rn((float)(int)fminf(fmaxf(v.x, -128.f), 127.f));
        pk.h[1] = __float2half_rn((float)(int)fminf(fmaxf(v.y, -128.f), 127.f));
        pk.h[2] = __float2half_rn((float)(int)fminf(fmaxf(v.z, -128.f), 127.f));
        pk.h[3] = __float2half_rn((float)(int)fminf(fmaxf(v.w, -128.f), 127.f));
        *(uint2*)&tile[c * 60 + qg * 4] = pk.u;
    }
    __syncthreads();

    uint4* dst = (uint4*)(g_xh + (size_t)np * (W_IN * C_IN));
    for (int i = threadIdx.x; i < 448; i += 256) {
        int q = i >> 3, c8 = i & 7;
        union { __half h[8]; uint4 u; } pk;
#pragma unroll
        for (int j = 0; j < 8; j++) pk.h[j] = tile[(c8 * 8 + j) * 60 + q];
        dst[q * 8 + c8] = pk.u;
    }
}

/* == main: fp16 HMMA implicit-GEMM, reg-pressure-aware inner loop ========== */
extern __shared__ unsigned char smem_raw[];

__global__ void __launch_bounds__(256, 2)
conv_kernel(const float* __restrict__ bias, float* __restrict__ out) {
    unsigned char* sm = smem_raw;
    int*   in_off  = (int*)sm;                 /* [128] NHWC element offset */
    int*   out_off = (int*)(sm + 512);         /* [128] */
    float* bias_s  = (float*)(sm + 1024);      /* [128] */
    const uint32_t smem_base = smem_u32(sm);
    const int tid = threadIdx.x;

    if (tid < 128) {
        int gm  = blockIdx.x * M_TILE + tid;
        int n   = gm / PQ;
        int rem = gm - n * PQ;
        int p   = rem / W_OUT;
        int q   = rem - p * W_OUT;
        in_off[tid]  = ((n * H_IN + p) * W_IN + q) * C_IN;
        out_off[tid] = n * (K_OUT * PQ) + rem;
        bias_s[tid]  = bias[tid];
    }
    __syncthreads();

    /* hoist per-thread A offsets (4 pixels per thread, fixed seg) */
    const int seg = tid & 7;                   /* 8 x 16B per pixel row */
    const int px0 = tid >> 3;
    int a_off[4];
#pragma unroll
    for (int j = 0; j < 4; j++) a_off[j] = in_off[px0 + 32 * j];

    const int bk  = tid >> 4;                  /* B: k-row base             */
    const int bc  = tid & 15;                  /* B: 16B chunk within k-row */

    auto load_stage = [&](int tap, int st) {
        uint32_t base = smem_base + OFF_STG + st * STAGE;
        int r = tap / 3, s = tap - 3 * (tap / 3);
        int tap_e = (r * W_IN + s) * C_IN;
        const unsigned char* xb = (const unsigned char*)g_xh;
#pragma unroll
        for (int j = 0; j < 4; j++) {
            int px = px0 + 32 * j;
            const void* src = xb + (size_t)(a_off[j] + tap_e) * 2 + seg * 16;
            CP16(base + px * (LDA_H * 2) + seg * 16, src);
        }
        const unsigned char* wb =
            (const unsigned char*)(g_wh + tap * (C_IN * K_OUT));
#pragma unroll
        for (int j = 0; j < 4; j++) {
            int k = bk + 16 * j;
            CP16(base + A_BYTES + k * (LDB_H * 2) + bc * 16,
                 wb + k * 256 + bc * 16);
        }
    };

    const int warp_m = (tid >> 5) & 1;
    const int warp_n = (tid >> 6);
    const int m0 = warp_m * 64;
    const int n0 = warp_n * 32;

    wmma::fragment<wmma::accumulator, 16, 16, 16, float> acc[4][2];
#pragma unroll
    for (int i = 0; i < 4; i++)
#pragma unroll
        for (int j = 0; j < 2; j++)
            wmma::fill_fragment(acc[i][j], 0.0f);

    load_stage(0, 0);
    CP_COMMIT();

    for (int t = 0; t < NTAPS; t++) {
        int st = t & 1;
        CP_WAIT0();                 /* stage st data landed                  */
        __syncthreads();            /* + all warps done with stage st^1 MMA */
        if (t < NTAPS - 1) {        /* prefetch t+1 overlaps MMA(t)          */
            load_stage(t + 1, st ^ 1);
            CP_COMMIT();
        }

        const __half* As = (const __half*)(sm + OFF_STG + st * STAGE)
                         + m0 * LDA_H;
        const __half* Bs = (const __half*)(sm + OFF_STG + st * STAGE
                                           + A_BYTES) + n0;
#pragma unroll
        for (int kk = 0; kk < 4; kk++) {
            /* reduced peak live set: b[2] + a-pair (streamed) + acc = 96 regs */
            wmma::fragment<wmma::matrix_b, 16, 16, 16, __half,
                           wmma::row_major> bf[2];
            wmma::fragment<wmma::matrix_a, 16, 16, 16, __half,
                           wmma::row_major> af[2];
            wmma::load_matrix_sync(bf[0], Bs + (kk * 16) * LDB_H, LDB_H);
            wmma::load_matrix_sync(bf[1], Bs + (kk * 16) * LDB_H + 16, LDB_H);
            wmma::load_matrix_sync(af[0], As + kk * 16, LDA_H);
#pragma unroll
            for (int i = 0; i < 4; i++) {
                if (i < 3)
                    wmma::load_matrix_sync(af[(i + 1) & 1],
                        As + (i + 1) * 16 * LDA_H + kk * 16, LDA_H);
                wmma::mma_sync(acc[i][0], af[i & 1], bf[0], acc[i][0]);
                wmma::mma_sync(acc[i][1], af[i & 1], bf[1], acc[i][1]);
            }
        }
    }
    __syncthreads();   /* all warps done reading smem before Os overwrite */

    /* ---- epilogue: stage [ko][m] fp32 in smem, coalesced NCHW stores ----- */
    float* Os = (float*)(sm + OFF_STG);
#pragma unroll
    for (int i = 0; i < 4; i++)
#pragma unroll
        for (int j = 0; j < 2; j++)
            wmma::store_matrix_sync(Os + (n0 + j * 16) * LDO + (m0 + i * 16),
                                    acc[i][j], LDO, wmma::mem_col_major);
    __syncthreads();

#pragma unroll
    for (int j = 0; j < 64; j++) {
        int i  = tid + j * 256;
        int ko = i >> 7;
        int m  = i & 127;
        out[out_off[m] + ko * PQ] = Os[ko * LDO + m] + bias_s[ko];
    }
}

/* ========================================================================= */
extern "C" void kernel_launch(void* const* d_in, const int* in_sizes, int n_in,
                              void* d_out, int out_size) {
    const float* x    = (const float*)d_in[0];
    const float* w    = (const float*)d_in[1];
    const float* bias = (const float*)d_in[2];
    float* out = (float*)d_out;

    cudaFuncSetAttribute(conv_kernel,
                         cudaFuncAttributeMaxDynamicSharedMemorySize,
                         SMEM_TOTAL);

    prep_kernel<<<N_IMG * H_IN + 288, 256>>>(x, w);
    conv_kernel<<<NCTA, 256, SMEM_TOTAL>>>(bias, out);
}